// round 8
// baseline (speedup 1.0000x reference)
#include <cuda_runtime.h>
#include <cub/cub.cuh>
#include <stdint.h>

#define NMAX 2000000

// ---------------- static device scratch (no allocations allowed) ----------------
__device__ unsigned g_minb[4];            // ordered-uint encoded column mins of point_bxyz
__device__ unsigned g_hminE, g_hmaxE;     // ordered-uint encoded min/max of point_height
__device__ int      g_cmax[4];            // per-column max voxel coord (dims = cmax+1)
__device__ unsigned g_pack[NMAX];         // packed per-point voxel coords
__device__ int      g_bufA[NMAX];         // merge keys -> flags -> vidx_of_point
__device__ int      g_bufB[NMAX];         // sorted merge keys -> tval (as float)
__device__ int      g_bufC[NMAX];         // identity values -> rank scan -> sorted tval (float)
__device__ int      g_bufD[NMAX];         // point index sorted by voxel
__device__ int      g_vstart[NMAX + 1];   // segment starts per voxel (= reference `offset`)
__device__ __align__(256) unsigned char g_cubtmp[64u << 20];

__device__ __forceinline__ unsigned fenc(float f) {
    unsigned u = __float_as_uint(f);
    return (u & 0x80000000u) ? ~u : (u | 0x80000000u);
}
__device__ __forceinline__ float fdec(unsigned u) {
    return __uint_as_float((u & 0x80000000u) ? (u ^ 0x80000000u) : ~u);
}

// ---------------- kernels ----------------
__global__ void k_init() {
    int t = threadIdx.x;
    if (t < 4) { g_minb[t] = 0xFFFFFFFFu; g_cmax[t] = 0; }
    if (t == 0) { g_hminE = 0xFFFFFFFFu; g_hmaxE = 0u; }
}

__global__ void k_minmax(const float4* __restrict__ bxyz, const float* __restrict__ h, int N) {
    unsigned m0 = ~0u, m1 = ~0u, m2 = ~0u, m3 = ~0u, hm = ~0u, hM = 0u;
    for (int i = blockIdx.x * blockDim.x + threadIdx.x; i < N; i += gridDim.x * blockDim.x) {
        float4 p = bxyz[i];
        m0 = min(m0, fenc(p.x)); m1 = min(m1, fenc(p.y));
        m2 = min(m2, fenc(p.z)); m3 = min(m3, fenc(p.w));
        unsigned he = fenc(h[i]);
        hm = min(hm, he); hM = max(hM, he);
    }
    __shared__ unsigned s[6];
    if (threadIdx.x < 6) s[threadIdx.x] = (threadIdx.x == 5) ? 0u : 0xFFFFFFFFu;
    __syncthreads();
    atomicMin(&s[0], m0); atomicMin(&s[1], m1); atomicMin(&s[2], m2); atomicMin(&s[3], m3);
    atomicMin(&s[4], hm); atomicMax(&s[5], hM);
    __syncthreads();
    if (threadIdx.x == 0) {
        atomicMin(&g_minb[0], s[0]); atomicMin(&g_minb[1], s[1]);
        atomicMin(&g_minb[2], s[2]); atomicMin(&g_minb[3], s[3]);
        atomicMin(&g_hminE, s[4]);   atomicMax(&g_hmaxE, s[5]);
    }
}

// per-point voxel coords; writes point_coords output (as float), packs coords, tracks dims
__global__ void k_coords(const float4* __restrict__ bxyz, const float* __restrict__ vs,
                         float4* __restrict__ out_pc, int N) {
    __shared__ int sm[4];
    if (threadIdx.x < 4) sm[threadIdx.x] = 0;
    __syncthreads();
    int i = blockIdx.x * blockDim.x + threadIdx.x;
    if (i < N) {
        float4 p = bxyz[i];
        float v0 = __ldg(vs + 0), v1 = __ldg(vs + 1), v2 = __ldg(vs + 2), v3 = __ldg(vs + 3);
        // pc_min is column-wise min so p - min >= 0; voxel sizes are powers of 2 -> exact
        int c0 = (int)floorf((p.x - fdec(g_minb[0])) / v0);
        int c1 = (int)floorf((p.y - fdec(g_minb[1])) / v1);
        int c2 = (int)floorf((p.z - fdec(g_minb[2])) / v2);
        int c3 = (int)floorf((p.w - fdec(g_minb[3])) / v3);
        out_pc[i] = make_float4((float)c0, (float)c1, (float)c2, (float)c3);
        g_pack[i] = ((unsigned)c0 << 30) | ((unsigned)c1 << 20) | ((unsigned)c2 << 10) | (unsigned)c3;
        atomicMax(&sm[0], c0); atomicMax(&sm[1], c1); atomicMax(&sm[2], c2); atomicMax(&sm[3], c3);
    }
    __syncthreads();
    if (threadIdx.x < 4) atomicMax(&g_cmax[threadIdx.x], sm[threadIdx.x]);
}

__global__ void k_merge(int N) {
    int i = blockIdx.x * blockDim.x + threadIdx.x;
    if (i >= N) return;
    unsigned pk = g_pack[i];
    int d1 = g_cmax[1] + 1, d2 = g_cmax[2] + 1, d3 = g_cmax[3] + 1;
    int c0 = (int)(pk >> 30), c1 = (int)((pk >> 20) & 1023u);
    int c2 = (int)((pk >> 10) & 1023u), c3 = (int)(pk & 1023u);
    g_bufA[i] = ((c0 * d1 + c1) * d2 + c2) * d3 + c3;
    g_bufC[i] = i;
}

__global__ void k_flags(int N) {
    int i = blockIdx.x * blockDim.x + threadIdx.x;
    if (i >= N) return;
    g_bufA[i] = (i == 0 || g_bufB[i] != g_bufB[i - 1]) ? 1 : 0;
}

// per sorted position: voxel_index, vidx_of_point, segment starts; heads emit voxel geometry
__global__ void k_unq(const float* __restrict__ vs, float* __restrict__ out,
                      long long V, int N) {
    int i = blockIdx.x * blockDim.x + threadIdx.x;
    if (i >= N) return;
    int vid = g_bufC[i] - 1;          // inclusive scan -> 0-based rank
    int p   = g_bufD[i];
    out[52 * V + p] = (float)vid;     // voxel_index output
    g_bufA[p] = vid;                  // vidx per original point (bufA flags are dead)
    bool head = (i == 0) || (g_bufB[i] != g_bufB[i - 1]);
    if (i == N - 1) g_vstart[vid + 1] = N;
    if (head) {
        g_vstart[vid] = i;
        int m = g_bufB[i];
        int d1 = g_cmax[1] + 1, d2 = g_cmax[2] + 1, d3 = g_cmax[3] + 1;
        int c3 = m % d3; m /= d3;
        int c2 = m % d2; m /= d2;
        int c1 = m % d1;
        int c0 = m / d1;
        float* unq = out + 11 * V + 4LL * vid;
        unq[0] = (float)c0; unq[1] = (float)c1; unq[2] = (float)c2; unq[3] = (float)c3;
        float v1 = __ldg(vs + 1), v2 = __ldg(vs + 2), v3 = __ldg(vs + 3);
        // (c*vs + pc_min) + vs/2, no FMA contraction (match XLA elementwise ops)
        float ce1 = __fadd_rn(__fadd_rn(__fmul_rn((float)c1, v1), fdec(g_minb[1])), 0.5f * v1);
        float ce2 = __fadd_rn(__fadd_rn(__fmul_rn((float)c2, v2), fdec(g_minb[2])), 0.5f * v2);
        float ce3 = __fadd_rn(__fadd_rn(__fmul_rn((float)c3, v3), fdec(g_minb[3])), 0.5f * v3);
        out[4 * V + 3LL * vid + 0] = ce1;  // voxel_center
        out[4 * V + 3LL * vid + 1] = ce2;
        out[4 * V + 3LL * vid + 2] = ce3;
        out[7 * V + 4LL * vid + 1] = ce1;  // voxel_bcenter[1:4]
        out[7 * V + 4LL * vid + 2] = ce2;
        out[7 * V + 4LL * vid + 3] = ce3;
    }
}

// one warp per voxel: segmented means (coalesced 128B feat rows per point)
__global__ void k_agg(const float* __restrict__ feat, const float* __restrict__ bxyz,
                      float* __restrict__ out, long long V) {
    long long t = (long long)blockIdx.x * blockDim.x + threadIdx.x;
    long long w = t >> 5;
    int lane = (int)(t & 31);
    if (w >= V) return;
    int s = g_vstart[w], e = g_vstart[w + 1];
    float sf = 0.f, sb = 0.f;
    for (int k = s; k < e; k++) {
        int p = g_bufD[k];
        sf += __ldg(feat + (long long)p * 32 + lane);
        if (lane < 4) sb += __ldg(bxyz + (long long)p * 4 + lane);
    }
    float fc = (float)(e - s);
    out[19 * V + w * 32 + lane] = sf / fc;                 // voxel_feat
    if (lane < 4) {
        float m = sb / fc;
        out[15 * V + w * 4 + lane] = m;                    // voxel_bxyz
        if (lane == 0) {
            out[7 * V + w * 4] = m;                        // voxel_bcenter[0]
            out[w] = rintf(m);                             // voxel_batch_index (round half-even)
        } else {
            out[V + w * 3 + (lane - 1)] = m;               // voxel_xyz
        }
    }
}

__global__ void k_tval(const float* __restrict__ h, int N) {
    int i = blockIdx.x * blockDim.x + threadIdx.x;
    if (i >= N) return;
    float hmn = fdec(g_hminE), hmx = fdec(g_hmaxE);
    // (h - min) + vidx*max, no contraction — must match XLA's separate mul/add
    float t = __fadd_rn(h[i] - hmn, __fmul_rn((float)g_bufA[i], hmx));
    reinterpret_cast<float*>(g_bufB)[i] = t;
}

__global__ void k_median(float* __restrict__ out, long long V) {
    long long v = (long long)blockIdx.x * blockDim.x + threadIdx.x;
    if (v >= V) return;
    int s = g_vstart[v];
    int c = g_vstart[v + 1] - s;
    float med = reinterpret_cast<float*>(g_bufC)[s + (c >> 1)];
    out[51 * V + v] = med - __fmul_rn((float)v, fdec(g_hmaxE));
}

// ---------------- host launcher (graph-capturable: kernels + CUB only) ----------------
extern "C" void kernel_launch(void* const* d_in, const int* in_sizes, int n_in,
                              void* d_out, int out_size) {
    // identify inputs by element count: vs=4, h=N, bxyz=4N, feat=32N
    int idx_vs = -1;
    for (int k = 0; k < n_in; k++) if (in_sizes[k] == 4) idx_vs = k;
    int others[3], no = 0;
    for (int k = 0; k < n_in && no < 3; k++) if (k != idx_vs) others[no++] = k;
    // sort the 3 remaining by size ascending
    for (int a = 0; a < 2; a++)
        for (int b = a + 1; b < 3; b++)
            if (in_sizes[others[b]] < in_sizes[others[a]]) { int t = others[a]; others[a] = others[b]; others[b] = t; }
    const float* h    = (const float*)d_in[others[0]];
    const float* bxyz = (const float*)d_in[others[1]];
    const float* feat = (const float*)d_in[others[2]];
    const float* vs   = (const float*)d_in[idx_vs];
    long long N = in_sizes[others[0]];
    if (N <= 0 || N > NMAX) return;
    long long V = ((long long)out_size - 5LL * N) / 52LL;
    if (V <= 0) return;
    float* out = (float*)d_out;

    void *pA, *pB, *pC, *pD, *pT;
    cudaGetSymbolAddress(&pA, g_bufA);
    cudaGetSymbolAddress(&pB, g_bufB);
    cudaGetSymbolAddress(&pC, g_bufC);
    cudaGetSymbolAddress(&pD, g_bufD);
    cudaGetSymbolAddress(&pT, g_cubtmp);

    int Bn = (int)((N + 255) / 256);
    k_init<<<1, 32>>>();
    k_minmax<<<1184, 256>>>((const float4*)bxyz, h, (int)N);
    k_coords<<<Bn, 256>>>((const float4*)bxyz, vs, (float4*)(out + 52 * V + N), (int)N);
    k_merge<<<Bn, 256>>>((int)N);

    size_t tb = 0;
    cub::DeviceRadixSort::SortPairs(nullptr, tb, (const int*)pA, (int*)pB,
                                    (const int*)pC, (int*)pD, (int)N, 0, 32, (cudaStream_t)0);
    if (tb <= sizeof(g_cubtmp))
        cub::DeviceRadixSort::SortPairs(pT, tb, (const int*)pA, (int*)pB,
                                        (const int*)pC, (int*)pD, (int)N, 0, 32, (cudaStream_t)0);

    k_flags<<<Bn, 256>>>((int)N);

    tb = 0;
    cub::DeviceScan::InclusiveSum(nullptr, tb, (const int*)pA, (int*)pC, (int)N, (cudaStream_t)0);
    if (tb <= sizeof(g_cubtmp))
        cub::DeviceScan::InclusiveSum(pT, tb, (const int*)pA, (int*)pC, (int)N, (cudaStream_t)0);

    k_unq<<<Bn, 256>>>(vs, out, V, (int)N);

    long long wthreads = V * 32;
    k_agg<<<(int)((wthreads + 255) / 256), 256>>>(feat, bxyz, out, V);

    k_tval<<<Bn, 256>>>(h, (int)N);

    tb = 0;
    cub::DeviceRadixSort::SortKeys(nullptr, tb, (const float*)pB, (float*)pC,
                                   (int)N, 0, 32, (cudaStream_t)0);
    if (tb <= sizeof(g_cubtmp))
        cub::DeviceRadixSort::SortKeys(pT, tb, (const float*)pB, (float*)pC,
                                       (int)N, 0, 32, (cudaStream_t)0);

    k_median<<<(int)((V + 255) / 256), 256>>>(out, V);
}